// round 4
// baseline (speedup 1.0000x reference)
#include <cuda_runtime.h>
#include <cstdint>

#define N_    32
#define C_    64
#define H_    112
#define W_    112
#define COUT_ 64

// NHWC int8 quantized activations: [N][H][W][C], 64 B per pixel
__device__ __align__(16) int8_t g_xq[(size_t)N_ * H_ * W_ * C_];
// repacked weights: [cout][tap(kh*3+kw)][cin] int8
__device__ __align__(16) int8_t g_wt[COUT_ * 9 * C_];
// input dtype mode for int8-origin tensors: 0=int8, 1=int32, 2=float32
__device__ int g_mode;

// mode-dispatched integer read for w_q / s_exp / act_exp
__device__ __forceinline__ int read_q(const void* p, int i, int mode) {
    if (mode == 1) return ((const int*)p)[i];
    if (mode == 2) return (int)((const float*)p)[i];
    return (int)((const int8_t*)p)[i];
}

// ---------------------------------------------------------------------------
// Detect the serialized layout of int8-origin inputs from s_exp's byte pattern.
// s_exp values are in [-10,-3]:
//   int8   -> bytes b0..b3 all in [-10,-3]
//   int32  -> (v,0xFF,0xFF,0xFF): b1==b2==b3==-1
//   float32-> (0x00,0x00,hi,0xC0/0xC1): b0==b1==0
// ---------------------------------------------------------------------------
__global__ void detect_kernel(const int8_t* __restrict__ s_raw) {
    const int b0 = s_raw[0], b1 = s_raw[1], b2 = s_raw[2], b3 = s_raw[3];
    int m = 0;
    if (b1 == -1 && b2 == -1 && b3 == -1) m = 1;
    else if (b0 == 0 && b1 == 0)          m = 2;
    g_mode = m;
}

// ---------------------------------------------------------------------------
// Pass 1: quantize + NCHW->NHWC transpose (one block per (n,h))
// ---------------------------------------------------------------------------
__global__ void quant_kernel(const float* __restrict__ x,
                             const void* __restrict__ act_exp) {
    __shared__ int8_t s[W_ * 68];  // 68-byte pixel stride: conflict-free STS
    const int bid = blockIdx.x;
    const int n = bid / H_;
    const int h = bid % H_;
    const int ae = read_q(act_exp, 0, g_mode);
    const float inv = exp2f(-(float)ae);           // 1/step

    const float* xp = x + (size_t)n * C_ * H_ * W_ + (size_t)h * W_;
    for (int idx = threadIdx.x; idx < C_ * W_; idx += blockDim.x) {
        const int c = idx / W_;
        const int w = idx % W_;
        float v = xp[(size_t)c * H_ * W_ + w];
        v = fminf(fmaxf(v, -1.0f), 1.0f);
        float r = rintf(v * inv);                   // matches jnp.round (RNE)
        r = fminf(fmaxf(r, -127.0f), 127.0f);
        s[w * 68 + c] = (int8_t)(int)r;
    }
    __syncthreads();

    int8_t* dst = g_xq + ((size_t)(n * H_ + h) * W_) * C_;
    for (int idx = threadIdx.x; idx < W_ * 16; idx += blockDim.x) {
        const int px = idx >> 4;
        const int wi = idx & 15;
        uint32_t v = *(const uint32_t*)&s[px * 68 + wi * 4];
        ((uint32_t*)dst)[idx] = v;                  // fully coalesced
    }
}

// ---------------------------------------------------------------------------
// Weight repack: OIHW -> [cout][tap][cin], mode-aware source read
// ---------------------------------------------------------------------------
__global__ void wtrans_kernel(const void* __restrict__ wq) {
    const int mode = g_mode;
    for (int idx = threadIdx.x + blockIdx.x * blockDim.x;
         idx < COUT_ * 9 * C_; idx += blockDim.x * gridDim.x) {
        const int co  = idx / (9 * C_);
        const int rem = idx % (9 * C_);
        const int tap = rem / C_;
        const int ci  = rem % C_;
        g_wt[idx] = (int8_t)read_q(wq, (co * C_ + ci) * 9 + tap, mode);
    }
}

// ---------------------------------------------------------------------------
// Pass 2: dp4a conv. One block per (n,h): 112 output pixels x 64 couts.
//   smem: weights 64*9*64 B = 36864 B, acts 3 rows x 114 px x 80 B = 27360 B
//   warp w -> couts [8w, 8w+8); lane -> pixels {lane, lane+32, lane+64, lane+96}
// ---------------------------------------------------------------------------
#define ACT_PIX_STRIDE 80
#define SMEM_W_BYTES   (COUT_ * 9 * C_)                 // 36864
#define SMEM_A_BYTES   (3 * (W_ + 2) * ACT_PIX_STRIDE)  // 27360
#define SMEM_TOTAL     (SMEM_W_BYTES + SMEM_A_BYTES)    // 64224

__global__ __launch_bounds__(256, 2)
void conv_kernel(const void* __restrict__ s_exp,
                 const float*  __restrict__ bias,
                 const void* __restrict__ act_exp,
                 float* __restrict__ out) {
    extern __shared__ __align__(16) int8_t smem[];
    int*    w_s = (int*)smem;                 // [cout][tap][16 words]
    int8_t* a_s = smem + SMEM_W_BYTES;        // [3][114][80B]

    const int bid = blockIdx.x;
    const int n = bid / H_;
    const int h = bid % H_;
    const int tid = threadIdx.x;

    // --- load weights (coalesced int4 copies from repacked gmem) ---
    {
        const int4* src = (const int4*)g_wt;
        int4* dst = (int4*)w_s;
        #pragma unroll 3
        for (int i = tid; i < SMEM_W_BYTES / 16; i += 256) dst[i] = src[i];
    }
    // --- load 3 input rows with halo (zero-padded) ---
    {
        for (int i = tid; i < 3 * (W_ + 2) * 4; i += 256) {
            const int p  = i >> 2;            // 0..341
            const int vi = i & 3;             // 16-byte chunk within pixel
            const int r  = p / (W_ + 2);
            const int pl = p % (W_ + 2);      // 0..113, input col = pl-1
            const int pw = pl - 1;
            const int hin = h - 1 + r;
            int4 v = make_int4(0, 0, 0, 0);
            if ((unsigned)hin < H_ && (unsigned)pw < W_) {
                v = *(const int4*)(g_xq +
                    ((size_t)(n * H_ + hin) * W_ + pw) * C_ + vi * 16);
            }
            *(int4*)(a_s + (r * (W_ + 2) + pl) * ACT_PIX_STRIDE + vi * 16) = v;
        }
    }
    __syncthreads();

    const int lane  = tid & 31;
    const int warp  = tid >> 5;
    const int cbase = warp * 8;

    int acc[4][8];
    #pragma unroll
    for (int pg = 0; pg < 4; pg++)
        #pragma unroll
        for (int co = 0; co < 8; co++) acc[pg][co] = 0;

    #pragma unroll
    for (int kh = 0; kh < 3; kh++) {
        #pragma unroll
        for (int kw = 0; kw < 3; kw++) {
            const int tap = kh * 3 + kw;
            // per-pixel-group smem base pointers for this tap
            const int4* ap[4];
            #pragma unroll
            for (int pg = 0; pg < 4; pg++) {
                int p = lane + 32 * pg + kw;  // smem pixel index (w-1+kw -> w+kw)
                if (p > W_ + 1) p = W_ + 1;   // clamp for invalid lanes
                ap[pg] = (const int4*)(a_s + (kh * (W_ + 2) + p) * ACT_PIX_STRIDE);
            }
            // j-outer: only 4 activation int4s live at a time (low reg pressure)
            #pragma unroll
            for (int j = 0; j < 4; j++) {
                int4 a[4];
                #pragma unroll
                for (int pg = 0; pg < 4; pg++) a[pg] = ap[pg][j];
                #pragma unroll
                for (int co = 0; co < 8; co++) {
                    const int4 wv = ((const int4*)(w_s + (cbase + co) * 144
                                                   + tap * 16))[j];  // broadcast
                    #pragma unroll
                    for (int pg = 0; pg < 4; pg++) {
                        acc[pg][co] = __dp4a(a[pg].x, wv.x, acc[pg][co]);
                        acc[pg][co] = __dp4a(a[pg].y, wv.y, acc[pg][co]);
                        acc[pg][co] = __dp4a(a[pg].z, wv.z, acc[pg][co]);
                        acc[pg][co] = __dp4a(a[pg].w, wv.w, acc[pg][co]);
                    }
                }
            }
        }
    }

    // --- epilogue: acc * 2^(act_exp + s_exp[c]) + bias[c], NCHW output ---
    const int mode = g_mode;
    const float ae = (float)read_q(act_exp, 0, mode);
    #pragma unroll
    for (int co = 0; co < 8; co++) {
        const int c = cbase + co;
        const float sc = exp2f(ae + (float)read_q(s_exp, c, mode)); // exact pow2
        const float b  = bias[c];
        float* op = out + (((size_t)n * COUT_ + c) * H_ + h) * W_;
        #pragma unroll
        for (int pg = 0; pg < 4; pg++) {
            const int w = lane + 32 * pg;
            if (w < W_) op[w] = (float)acc[pg][co] * sc + b;
        }
    }
}

// ---------------------------------------------------------------------------
extern "C" void kernel_launch(void* const* d_in, const int* in_sizes, int n_in,
                              void* d_out, int out_size) {
    const float* x       = (const float*)d_in[0];
    const void*  wq      = d_in[1];
    const void*  s_exp   = d_in[2];
    const float* bias    = (const float*)d_in[3];
    const void*  act_exp = d_in[4];
    float* out = (float*)d_out;

    cudaFuncSetAttribute(conv_kernel,
                         cudaFuncAttributeMaxDynamicSharedMemorySize, SMEM_TOTAL);

    detect_kernel<<<1, 1>>>((const int8_t*)s_exp);
    quant_kernel<<<N_ * H_, 256>>>(x, act_exp);
    wtrans_kernel<<<4, 256>>>(wq);
    conv_kernel<<<N_ * H_, 256, SMEM_TOTAL>>>(s_exp, bias, act_exp, out);
}

// round 7
// speedup vs baseline: 2.2078x; 2.2078x over previous
#include <cuda_runtime.h>
#include <cstdint>

#define N_    32
#define C_    64
#define H_    112
#define W_    112
#define COUT_ 64

#define APAD        80                    // padded pixel stride (conflict-free ldmatrix)
#define A_ROW_BYTES (130 * APAD)          // 10400
#define A_BYTES     (3 * A_ROW_BYTES)     // 31200
#define B_TAP_BYTES (64 * APAD)           // 5120
#define B_BYTES     (9 * B_TAP_BYTES)     // 46080
#define AUX_BYTES   512
#define SMEM_DYN    (A_BYTES + B_BYTES + AUX_BYTES)   // 77792

// NHWC int8 quantized activations: [N][H][W][C]
__device__ __align__(16) int8_t g_xq[(size_t)N_ * H_ * W_ * C_];
// padded weight image: [tap][cout][80B: 64 ci + pad]
__device__ __align__(16) int8_t g_wtb[B_BYTES];
// input dtype mode for int8-origin tensors: 0=int8, 1=int32, 2=float32
__device__ int g_mode;

__device__ __forceinline__ int read_q(const void* p, int i, int mode) {
    if (mode == 1) return ((const int*)p)[i];
    if (mode == 2) return (int)((const float*)p)[i];
    return (int)((const int8_t*)p)[i];
}

__device__ __forceinline__ uint32_t smem_u32(const void* p) {
    uint32_t a;
    asm("{ .reg .u64 t; cvta.to.shared.u64 t, %1; cvt.u32.u64 %0, t; }" : "=r"(a) : "l"(p));
    return a;
}

#define LDSM4(r0, r1, r2, r3, addr)                                          \
    asm volatile("ldmatrix.sync.aligned.m8n8.x4.shared.b16 {%0,%1,%2,%3}, [%4];" \
                 : "=r"(r0), "=r"(r1), "=r"(r2), "=r"(r3) : "r"(addr))

#define MMA_S8(d, a0, a1, a2, a3, b0, b1)                                    \
    asm volatile("mma.sync.aligned.m16n8k32.row.col.s32.s8.s8.s32 "          \
                 "{%0,%1,%2,%3}, {%4,%5,%6,%7}, {%8,%9}, {%0,%1,%2,%3};"     \
                 : "+r"(d[0]), "+r"(d[1]), "+r"(d[2]), "+r"(d[3])            \
                 : "r"(a0), "r"(a1), "r"(a2), "r"(a3), "r"(b0), "r"(b1))

// ---------------------------------------------------------------------------
__global__ void detect_kernel(const int8_t* __restrict__ s_raw) {
    const int b0 = s_raw[0], b1 = s_raw[1], b2 = s_raw[2], b3 = s_raw[3];
    int m = 0;
    if (b1 == -1 && b2 == -1 && b3 == -1) m = 1;
    else if (b0 == 0 && b1 == 0)          m = 2;
    g_mode = m;
}

// ---------------------------------------------------------------------------
// quantize + NCHW->NHWC int8 (one block per (n,h))
// ---------------------------------------------------------------------------
__global__ void quant_kernel(const float* __restrict__ x,
                             const void* __restrict__ act_exp) {
    __shared__ int8_t s[W_ * 68];
    const int n = blockIdx.x / H_;
    const int h = blockIdx.x % H_;
    const float inv = exp2f(-(float)read_q(act_exp, 0, g_mode));

    const float* xp = x + (size_t)n * C_ * H_ * W_ + (size_t)h * W_;
    for (int idx = threadIdx.x; idx < C_ * W_; idx += blockDim.x) {
        const int c = idx / W_;
        const int w = idx % W_;
        float v = xp[(size_t)c * H_ * W_ + w];
        v = fminf(fmaxf(v, -1.0f), 1.0f);
        float r = rintf(v * inv);                   // RNE, matches jnp.round
        r = fminf(fmaxf(r, -127.0f), 127.0f);
        s[w * 68 + c] = (int8_t)(int)r;
    }
    __syncthreads();
    int8_t* dst = g_xq + ((size_t)(n * H_ + h) * W_) * C_;
    for (int idx = threadIdx.x; idx < W_ * 16; idx += blockDim.x) {
        const int px = idx >> 4;
        const int wi = idx & 15;
        ((uint32_t*)dst)[idx] = *(const uint32_t*)&s[px * 68 + wi * 4];
    }
}

// ---------------------------------------------------------------------------
// weights -> padded int8 image: [tap][co][80B ci-row]
// ---------------------------------------------------------------------------
__global__ void wprep_kernel(const void* __restrict__ wq) {
    const int mode = g_mode;
    for (int idx = threadIdx.x + blockIdx.x * blockDim.x;
         idx < 9 * 64 * 64; idx += blockDim.x * gridDim.x) {
        const int tap = idx / 4096;
        const int rem = idx % 4096;
        const int co  = rem / 64;
        const int ci  = rem % 64;
        g_wtb[tap * B_TAP_BYTES + co * APAD + ci] =
            (int8_t)read_q(wq, (co * C_ + ci) * 9 + tap, mode);
    }
}

// ---------------------------------------------------------------------------
// IMMA conv: CTA = (n, h). M=128 px (112 valid), N=64 co, K=576.
// 8 warps = 2 m-halves x 4 n-groups; warp tile m64 n16.
// ---------------------------------------------------------------------------
__global__ __launch_bounds__(256, 2)
void conv_kernel(const void* __restrict__ s_exp,
                 const float* __restrict__ bias,
                 const void* __restrict__ act_exp,
                 float* __restrict__ out) {
    extern __shared__ __align__(16) char smem[];
    const uint32_t sb = smem_u32(smem);
    float* s_scale = (float*)(smem + A_BYTES + B_BYTES);        // 64 floats
    float* s_bias  = s_scale + 64;                              // 64 floats

    const int tid  = threadIdx.x;
    const int wid  = tid >> 5;
    const int lane = tid & 31;
    const int n = blockIdx.x / H_;
    const int h = blockIdx.x % H_;
    const int mode = g_mode;

    // --- fill B: verbatim copy of padded weight image ---
    {
        const int4* src = (const int4*)g_wtb;
        int4* dst = (int4*)(smem + A_BYTES);
        #pragma unroll
        for (int i = tid; i < B_BYTES / 16; i += 256) dst[i] = src[i];
    }
    // --- fill A: 3 rows x 130 px x 64B, raw int8 copy with halo zero-fill ---
    for (int i = tid; i < 3 * 130 * 4; i += 256) {
        const int ch = i & 3;                 // 16B chunk within pixel
        const int p  = (i >> 2) % 130;        // buffer pixel (input col = p-1)
        const int r  = (i >> 2) / 130;        // row 0..2 (input h-1+r)
        const int hr = h - 1 + r;
        const int pw = p - 1;
        int4 v = make_int4(0, 0, 0, 0);
        if ((unsigned)hr < H_ && (unsigned)pw < W_)
            v = *(const int4*)(g_xq + ((size_t)(n * H_ + hr) * W_ + pw) * C_ + ch * 16);
        *(int4*)(smem + r * A_ROW_BYTES + p * APAD + ch * 16) = v;
    }
    // --- scales + bias ---
    if (tid < COUT_) {
        const float ae = (float)read_q(act_exp, 0, mode);
        s_scale[tid] = exp2f(ae + (float)read_q(s_exp, tid, mode));
        s_bias[tid]  = bias[tid];
    }
    __syncthreads();

    // --- warp tiling ---
    const int wm = wid & 1;                   // m half: pixels [64*wm, 64*wm+64)
    const int wn = wid >> 1;                  // n group: couts [16*wn, 16*wn+16)
    const int m_base = wm * 64;
    const int grp = lane >> 3;                // ldmatrix tile group 0..3
    const int rw  = lane & 7;                 // row within tile

    // B tiles: t0: n+0 klo, t1: n+0 khi, t2: n+8 klo, t3: n+8 khi
    const uint32_t b_addr0 = sb + A_BYTES
        + (uint32_t)((wn * 16 + ((grp & 2) ? 8 : 0) + rw) * APAD + ((grp & 1) ? 16 : 0));
    // A tiles: t0: rows+0 klo, t1: rows+8 klo, t2: rows+0 khi, t3: rows+8 khi
    const uint32_t a_addr0 = sb
        + (uint32_t)((((grp & 1) ? 8 : 0) + rw) * APAD + ((grp & 2) ? 16 : 0));

    int acc[4][2][4];
    #pragma unroll
    for (int i = 0; i < 4; i++)
        #pragma unroll
        for (int nt = 0; nt < 2; nt++)
            #pragma unroll
            for (int r = 0; r < 4; r++) acc[i][nt][r] = 0;

    #pragma unroll
    for (int tap = 0; tap < 9; tap++) {
        const int kh = tap / 3, kw = tap % 3;
        #pragma unroll
        for (int kk = 0; kk < 2; kk++) {
            uint32_t b0, b1, b2, b3;
            LDSM4(b0, b1, b2, b3, b_addr0 + tap * B_TAP_BYTES + kk * 32);
            #pragma unroll
            for (int i = 0; i < 4; i++) {
                uint32_t a0, a1, a2, a3;
                LDSM4(a0, a1, a2, a3,
                      a_addr0 + (kh * 130 + m_base + i * 16 + kw) * APAD + kk * 32);
                MMA_S8(acc[i][0], a0, a1, a2, a3, b0, b1);
                MMA_S8(acc[i][1], a0, a1, a2, a3, b2, b3);
            }
        }
    }
    __syncthreads();   // weights no longer needed; reuse region as float stage

    // --- stage acc -> smem[px][65 floats] with scale+bias ---
    float* stage = (float*)(smem + A_BYTES);
    {
        const int q = lane >> 2;              // row-in-tile 0..7
        const int t = lane & 3;
        #pragma unroll
        for (int i = 0; i < 4; i++) {
            #pragma unroll
            for (int nt = 0; nt < 2; nt++) {
                const int c = wn * 16 + nt * 8 + 2 * t;
                const float sc0 = s_scale[c],     b0f = s_bias[c];
                const float sc1 = s_scale[c + 1], b1f = s_bias[c + 1];
                const int px0 = m_base + i * 16 + q;
                stage[px0 * 65 + c]           = (float)acc[i][nt][0] * sc0 + b0f;
                stage[px0 * 65 + c + 1]       = (float)acc[i][nt][1] * sc1 + b1f;
                stage[(px0 + 8) * 65 + c]     = (float)acc[i][nt][2] * sc0 + b0f;
                stage[(px0 + 8) * 65 + c + 1] = (float)acc[i][nt][3] * sc1 + b1f;
            }
        }
    }
    __syncthreads();

    // --- coalesced NCHW store: 64 couts x 112 px ---
    #pragma unroll
    for (int it = 0; it < 32; it++) {
        const int f = tid + it * 256;
        const int c = f >> 7;
        const int w = f & 127;
        if (w < W_)
            out[(((size_t)n * COUT_ + c) * H_ + h) * W_ + w] = stage[w * 65 + c];
    }
}

// ---------------------------------------------------------------------------
extern "C" void kernel_launch(void* const* d_in, const int* in_sizes, int n_in,
                              void* d_out, int out_size) {
    const float* x       = (const float*)d_in[0];
    const void*  wq      = d_in[1];
    const void*  s_exp   = d_in[2];
    const float* bias    = (const float*)d_in[3];
    const void*  act_exp = d_in[4];
    float* out = (float*)d_out;

    cudaFuncSetAttribute(conv_kernel,
                         cudaFuncAttributeMaxDynamicSharedMemorySize, SMEM_DYN);

    detect_kernel<<<1, 1>>>((const int8_t*)s_exp);
    quant_kernel<<<N_ * H_, 256>>>(x, act_exp);
    wprep_kernel<<<16, 256>>>(wq);
    conv_kernel<<<N_ * H_, 256, SMEM_DYN>>>(s_exp, bias, act_exp, out);
}